// round 5
// baseline (speedup 1.0000x reference)
#include <cuda_runtime.h>
#include <cuda_bf16.h>
#include <cstdint>

#define N_MAX   100000
#define E_MAX   3200000
#define C_DIM   40
#define F_DIM   128
#define NCOPY   64
#define NB_MAX  ((N_MAX + 255) / 256)

// ---------------- scratch (device globals; no allocation) ----------------
__device__ int   g_is64;
__device__ int   g_hist[(size_t)NCOPY * N_MAX];   // counts, then fill cursors
__device__ int   g_deg[N_MAX];                    // in-degree (excl self)
__device__ int   g_off[N_MAX];                    // CSR start
__device__ int   g_part[NB_MAX];                  // per-block deg sums -> exclusive
__device__ int   g_adj[E_MAX];
__device__ float g_dinv[N_MAX];
__device__ __align__(16) float g_bufA[(size_t)N_MAX * C_DIM];
__device__ __align__(16) float g_bufB[(size_t)N_MAX * C_DIM];

// ---------------- kernels ----------------

// Detect int64 vs int32 edge buffer (node ids small -> int64 high words all 0).
__global__ void k_detect(const int* __restrict__ ei32, int E) {
    if (blockIdx.x == 0 && threadIdx.x == 0) {
        int n = E < 64 ? E : 64;
        int is64 = 1;
        for (int i = 0; i < n; ++i)
            if (ei32[2 * i + 1] != 0) { is64 = 0; break; }
        g_is64 = is64;
    }
}

__global__ void k_zero_hist() {
    size_t i = (size_t)blockIdx.x * blockDim.x + threadIdx.x;
    size_t tot = (size_t)NCOPY * N_MAX / 4;
    if (i < tot) ((int4*)g_hist)[i] = make_int4(0, 0, 0, 0);
}

__device__ __forceinline__ void load_edge(const int* ei32, int E, int e, int& r, int& c) {
    if (g_is64) { r = ei32[2 * e]; c = ei32[2 * (E + e)]; }
    else        { r = ei32[e];     c = ei32[E + e]; }
}

// Privatized histogram of col: copy = e / ce.
__global__ void k_hist(const int* __restrict__ ei32, int E, int ce) {
    int e = blockIdx.x * blockDim.x + threadIdx.x;
    if (e >= E) return;
    int r, c;
    load_edge(ei32, E, e, r, c);
    int k = e / ce;
    atomicAdd(&g_hist[(size_t)k * N_MAX + c], 1);
}

// deg[n] = sum over copies; dinv = rsqrt(deg+1); per-block deg sums -> g_part.
__global__ void k_deg(int N) {
    __shared__ int red[256];
    int n = blockIdx.x * 256 + threadIdx.x;
    int d = 0;
    if (n < N) {
#pragma unroll 8
        for (int k = 0; k < NCOPY; ++k) d += g_hist[(size_t)k * N_MAX + n];
        g_deg[n] = d;
        g_dinv[n] = rsqrtf((float)(d + 1));
    }
    red[threadIdx.x] = d;
    __syncthreads();
    for (int s = 128; s > 0; s >>= 1) {
        if (threadIdx.x < s) red[threadIdx.x] += red[threadIdx.x + s];
        __syncthreads();
    }
    if (threadIdx.x == 0) g_part[blockIdx.x] = red[0];
}

// Exclusive scan over block partials (NB <= 512), single block.
__global__ void k_scanp(int NB) {
    __shared__ int s[512];
    int t = threadIdx.x;
    int v = (t < NB) ? g_part[t] : 0;
    s[t] = v;
    __syncthreads();
    for (int o = 1; o < 512; o <<= 1) {
        int u = (t >= o) ? s[t - o] : 0;
        __syncthreads();
        s[t] += u;
        __syncthreads();
    }
    if (t < NB) g_part[t] = s[t] - v;   // exclusive
}

// off[n] = global exclusive prefix of deg; convert hist counts -> fill cursors.
__global__ void k_base(int N) {
    __shared__ int s[256];
    int t = threadIdx.x;
    int n = blockIdx.x * 256 + t;
    int d = (n < N) ? g_deg[n] : 0;
    s[t] = d;
    __syncthreads();
    for (int o = 1; o < 256; o <<= 1) {
        int u = (t >= o) ? s[t - o] : 0;
        __syncthreads();
        s[t] += u;
        __syncthreads();
    }
    if (n < N) {
        int off = g_part[blockIdx.x] + s[t] - d;
        g_off[n] = off;
        int run = off;
#pragma unroll 8
        for (int k = 0; k < NCOPY; ++k) {
            size_t idx = (size_t)k * N_MAX + n;
            int c = g_hist[idx];
            g_hist[idx] = run;
            run += c;
        }
    }
}

// Fill CSR using privatized cursors (uncontended atomics).
__global__ void k_fill(const int* __restrict__ ei32, int E, int ce) {
    int e = blockIdx.x * blockDim.x + threadIdx.x;
    if (e >= E) return;
    int r, c;
    load_edge(ei32, E, e, r, c);
    int k = e / ce;
    int p = atomicAdd(&g_hist[(size_t)k * N_MAX + c], 1);
    g_adj[p] = r;
}

// bufB[n,:] = dinv[n] * (X[n,:] @ W^T)   (prescale fused into GEMM epilogue)
__global__ void k_gemm(const float* __restrict__ X, const float* __restrict__ W,
                       float* __restrict__ Y, int N) {
    __shared__ float ws[C_DIM * F_DIM];
    for (int i = threadIdx.x; i < C_DIM * F_DIM; i += blockDim.x) ws[i] = W[i];
    __syncthreads();

    int n = blockIdx.x * blockDim.x + threadIdx.x;
    if (n >= N) return;

    const float4* xp = (const float4*)(X + (size_t)n * F_DIM);
    float acc[C_DIM];
#pragma unroll
    for (int c = 0; c < C_DIM; ++c) acc[c] = 0.0f;

#pragma unroll 1
    for (int ch = 0; ch < 8; ++ch) {
        float4 xv[4];
#pragma unroll
        for (int j = 0; j < 4; ++j) xv[j] = xp[ch * 4 + j];
#pragma unroll
        for (int c = 0; c < C_DIM; ++c) {
            const float4* wp = (const float4*)(ws + c * F_DIM + ch * 16);
            float s = acc[c];
#pragma unroll
            for (int j = 0; j < 4; ++j) {
                float4 w = wp[j];
                s += xv[j].x * w.x + xv[j].y * w.y + xv[j].z * w.z + xv[j].w * w.w;
            }
            acc[c] = s;
        }
    }

    float dn = g_dinv[n];
    float4* yp = (float4*)(Y + (size_t)n * C_DIM);
#pragma unroll
    for (int k = 0; k < 10; ++k)
        yp[k] = make_float4(dn * acc[4 * k], dn * acc[4 * k + 1],
                            dn * acc[4 * k + 2], dn * acc[4 * k + 3]);
}

#define ACC1(A, V) { A.x += V.x; A.y += V.y; A.z += V.z; A.w += V.w; }

// hop 1: dst[n] = dinv[n]^2 * (src[n] + sum src[r]).  2 thr/node, 5 float4 each.
__global__ void k_gather(const float4* __restrict__ src, float4* __restrict__ dst,
                         int N) {
    int t = blockIdx.x * blockDim.x + threadIdx.x;
    int n = t >> 1;
    if (n >= N) return;
    int part = (t & 1) * 5;

    int beg = g_off[n];
    int end = beg + g_deg[n];

    const float4* sp = src + (size_t)n * 10 + part;
    float4 a0 = sp[0], a1 = sp[1], a2 = sp[2], a3 = sp[3], a4 = sp[4];

    int k = beg;
    for (; k + 2 <= end; k += 2) {
        int r0 = g_adj[k], r1 = g_adj[k + 1];
        const float4* v0 = src + (size_t)r0 * 10 + part;
        const float4* v1 = src + (size_t)r1 * 10 + part;
        float4 u0 = v0[0], u1 = v0[1], u2 = v0[2], u3 = v0[3], u4 = v0[4];
        float4 w0 = v1[0], w1 = v1[1], w2 = v1[2], w3 = v1[3], w4 = v1[4];
        ACC1(a0, u0) ACC1(a1, u1) ACC1(a2, u2) ACC1(a3, u3) ACC1(a4, u4)
        ACC1(a0, w0) ACC1(a1, w1) ACC1(a2, w2) ACC1(a3, w3) ACC1(a4, w4)
    }
    if (k < end) {
        int r0 = g_adj[k];
        const float4* v0 = src + (size_t)r0 * 10 + part;
        float4 u0 = v0[0], u1 = v0[1], u2 = v0[2], u3 = v0[3], u4 = v0[4];
        ACC1(a0, u0) ACC1(a1, u1) ACC1(a2, u2) ACC1(a3, u3) ACC1(a4, u4)
    }

    float dn = g_dinv[n];
    float sc = dn * dn;
    float4* dp = dst + (size_t)n * 10 + part;
    dp[0] = make_float4(sc * a0.x, sc * a0.y, sc * a0.z, sc * a0.w);
    dp[1] = make_float4(sc * a1.x, sc * a1.y, sc * a1.z, sc * a1.w);
    dp[2] = make_float4(sc * a2.x, sc * a2.y, sc * a2.z, sc * a2.w);
    dp[3] = make_float4(sc * a3.x, sc * a3.y, sc * a3.z, sc * a3.w);
    dp[4] = make_float4(sc * a4.x, sc * a4.y, sc * a4.z, sc * a4.w);
}

// hop 2 fused with bias + log_softmax. Pair (lane, lane^1) covers one node.
__global__ void k_gather_lsm(const float4* __restrict__ src,
                             const float4* __restrict__ bias4,
                             float* __restrict__ out, int N) {
    int t = blockIdx.x * blockDim.x + threadIdx.x;
    int n = t >> 1;
    if (n >= N) return;
    int part = (t & 1) * 5;

    int beg = g_off[n];
    int end = beg + g_deg[n];

    const float4* sp = src + (size_t)n * 10 + part;
    float4 a0 = sp[0], a1 = sp[1], a2 = sp[2], a3 = sp[3], a4 = sp[4];

    int k = beg;
    for (; k + 2 <= end; k += 2) {
        int r0 = g_adj[k], r1 = g_adj[k + 1];
        const float4* v0 = src + (size_t)r0 * 10 + part;
        const float4* v1 = src + (size_t)r1 * 10 + part;
        float4 u0 = v0[0], u1 = v0[1], u2 = v0[2], u3 = v0[3], u4 = v0[4];
        float4 w0 = v1[0], w1 = v1[1], w2 = v1[2], w3 = v1[3], w4 = v1[4];
        ACC1(a0, u0) ACC1(a1, u1) ACC1(a2, u2) ACC1(a3, u3) ACC1(a4, u4)
        ACC1(a0, w0) ACC1(a1, w1) ACC1(a2, w2) ACC1(a3, w3) ACC1(a4, w4)
    }
    if (k < end) {
        int r0 = g_adj[k];
        const float4* v0 = src + (size_t)r0 * 10 + part;
        float4 u0 = v0[0], u1 = v0[1], u2 = v0[2], u3 = v0[3], u4 = v0[4];
        ACC1(a0, u0) ACC1(a1, u1) ACC1(a2, u2) ACC1(a3, u3) ACC1(a4, u4)
    }

    float dn = g_dinv[n];
    float z[20];
    float4 av[5] = {a0, a1, a2, a3, a4};
#pragma unroll
    for (int i = 0; i < 5; ++i) {
        float4 b = bias4[part + i];
        z[4 * i + 0] = dn * av[i].x + b.x;
        z[4 * i + 1] = dn * av[i].y + b.y;
        z[4 * i + 2] = dn * av[i].z + b.z;
        z[4 * i + 3] = dn * av[i].w + b.w;
    }

    float mx = z[0];
#pragma unroll
    for (int i = 1; i < 20; ++i) mx = fmaxf(mx, z[i]);
    mx = fmaxf(mx, __shfl_xor_sync(0xffffffffu, mx, 1));

    float sum = 0.0f;
#pragma unroll
    for (int i = 0; i < 20; ++i) sum += __expf(z[i] - mx);
    sum += __shfl_xor_sync(0xffffffffu, sum, 1);

    float l = mx + logf(sum);
    float4* op = (float4*)(out + (size_t)n * C_DIM + part * 4);
#pragma unroll
    for (int i = 0; i < 5; ++i)
        op[i] = make_float4(z[4 * i] - l, z[4 * i + 1] - l,
                            z[4 * i + 2] - l, z[4 * i + 3] - l);
}

// ---------------- launch ----------------
extern "C" void kernel_launch(void* const* d_in, const int* in_sizes, int n_in,
                              void* d_out, int out_size) {
    const float* X    = (const float*)d_in[0];      // [N, 128]
    const float* W    = (const float*)d_in[1];      // [40, 128]
    const float* bias = (const float*)d_in[2];      // [40]
    const int*   ei   = (const int*)d_in[3];        // [2, E] int32 or int64
    (void)n_in;

    const int N = in_sizes[0] / F_DIM;
    const int E = in_sizes[3] / 2;
    const int ce = (E + NCOPY - 1) / NCOPY;
    float* out = (float*)d_out;
    (void)out_size;

    const int TB = 256;
    const int NB = (N + TB - 1) / TB;
    dim3 gN(NB);
    dim3 gE((E + TB - 1) / TB);
    dim3 gZ(((size_t)NCOPY * N_MAX / 4 + TB - 1) / TB);
    dim3 gG((2 * N + TB - 1) / TB);

    // dense CSR build, privatized counting sort
    k_detect<<<1, 32>>>(ei, E);
    k_zero_hist<<<gZ, TB>>>();
    k_hist<<<gE, TB>>>(ei, E, ce);
    k_deg<<<gN, TB>>>(N);
    k_scanp<<<1, 512>>>(NB);
    k_base<<<gN, TB>>>(N);
    k_fill<<<gE, TB>>>(ei, E, ce);

    // projection (128 -> 40) with D^{-1/2} prescale fused
    k_gemm<<<gN, TB>>>(X, W, g_bufB, N);

    // hop 1: bufB -> bufA (scale dinv^2)
    k_gather<<<gG, TB>>>((const float4*)g_bufB, (float4*)g_bufA, N);

    // hop 2 + bias + log_softmax, writes output directly
    k_gather_lsm<<<gG, TB>>>((const float4*)g_bufA, (const float4*)bias, out, N);
}

// round 6
// speedup vs baseline: 1.1673x; 1.1673x over previous
#include <cuda_runtime.h>
#include <cuda_bf16.h>
#include <cstdint>

#define N_MAX   100000
#define E_MAX   3200000
#define C_DIM   40
#define F_DIM   128
#define NCOPY   64
#define NB_MAX  ((N_MAX + 255) / 256)

// ---------------- scratch (device globals; no allocation) ----------------
__device__ int   g_is64;
__device__ int   g_hist[(size_t)NCOPY * N_MAX];   // counts, then fill cursors
__device__ int   g_deg[N_MAX];                    // in-degree (excl self)
__device__ int   g_off[N_MAX];                    // CSR start
__device__ int   g_part[NB_MAX];                  // per-block deg sums -> exclusive
__device__ int   g_adj[E_MAX];
__device__ float g_dinv[N_MAX];
__device__ __align__(16) float g_bufA[(size_t)N_MAX * C_DIM];
__device__ __align__(16) float g_bufB[(size_t)N_MAX * C_DIM];

// ---------------- CSR build (privatized counting sort; R5-proven) ----------------

__global__ void k_detect(const int* __restrict__ ei32, int E) {
    if (blockIdx.x == 0 && threadIdx.x == 0) {
        int n = E < 64 ? E : 64;
        int is64 = 1;
        for (int i = 0; i < n; ++i)
            if (ei32[2 * i + 1] != 0) { is64 = 0; break; }
        g_is64 = is64;
    }
}

__global__ void k_zero_hist() {
    size_t i = (size_t)blockIdx.x * blockDim.x + threadIdx.x;
    size_t tot = (size_t)NCOPY * N_MAX / 4;
    if (i < tot) ((int4*)g_hist)[i] = make_int4(0, 0, 0, 0);
}

__device__ __forceinline__ void load_edge(const int* ei32, int E, int e, int& r, int& c) {
    if (g_is64) { r = ei32[2 * e]; c = ei32[2 * (E + e)]; }
    else        { r = ei32[e];     c = ei32[E + e]; }
}

__global__ void k_hist(const int* __restrict__ ei32, int E, int ce) {
    int e = blockIdx.x * blockDim.x + threadIdx.x;
    if (e >= E) return;
    int r, c;
    load_edge(ei32, E, e, r, c);
    int k = e / ce;
    atomicAdd(&g_hist[(size_t)k * N_MAX + c], 1);
}

__global__ void k_deg(int N) {
    __shared__ int red[256];
    int n = blockIdx.x * 256 + threadIdx.x;
    int d = 0;
    if (n < N) {
#pragma unroll 8
        for (int k = 0; k < NCOPY; ++k) d += g_hist[(size_t)k * N_MAX + n];
        g_deg[n] = d;
        g_dinv[n] = rsqrtf((float)(d + 1));
    }
    red[threadIdx.x] = d;
    __syncthreads();
    for (int s = 128; s > 0; s >>= 1) {
        if (threadIdx.x < s) red[threadIdx.x] += red[threadIdx.x + s];
        __syncthreads();
    }
    if (threadIdx.x == 0) g_part[blockIdx.x] = red[0];
}

__global__ void k_scanp(int NB) {
    __shared__ int s[512];
    int t = threadIdx.x;
    int v = (t < NB) ? g_part[t] : 0;
    s[t] = v;
    __syncthreads();
    for (int o = 1; o < 512; o <<= 1) {
        int u = (t >= o) ? s[t - o] : 0;
        __syncthreads();
        s[t] += u;
        __syncthreads();
    }
    if (t < NB) g_part[t] = s[t] - v;   // exclusive
}

__global__ void k_base(int N) {
    __shared__ int s[256];
    int t = threadIdx.x;
    int n = blockIdx.x * 256 + t;
    int d = (n < N) ? g_deg[n] : 0;
    s[t] = d;
    __syncthreads();
    for (int o = 1; o < 256; o <<= 1) {
        int u = (t >= o) ? s[t - o] : 0;
        __syncthreads();
        s[t] += u;
        __syncthreads();
    }
    if (n < N) {
        int off = g_part[blockIdx.x] + s[t] - d;
        g_off[n] = off;
        int run = off;
#pragma unroll 8
        for (int k = 0; k < NCOPY; ++k) {
            size_t idx = (size_t)k * N_MAX + n;
            int c = g_hist[idx];
            g_hist[idx] = run;
            run += c;
        }
    }
}

__global__ void k_fill(const int* __restrict__ ei32, int E, int ce) {
    int e = blockIdx.x * blockDim.x + threadIdx.x;
    if (e >= E) return;
    int r, c;
    load_edge(ei32, E, e, r, c);
    int k = e / ce;
    int p = atomicAdd(&g_hist[(size_t)k * N_MAX + c], 1);
    g_adj[p] = r;
}

// ---------------- compute ----------------

// bufB[n,:] = dinv[n] * (X[n,:] @ W^T)
__global__ void k_gemm(const float* __restrict__ X, const float* __restrict__ W,
                       float* __restrict__ Y, int N) {
    __shared__ float ws[C_DIM * F_DIM];
    for (int i = threadIdx.x; i < C_DIM * F_DIM; i += blockDim.x) ws[i] = W[i];
    __syncthreads();

    int n = blockIdx.x * blockDim.x + threadIdx.x;
    if (n >= N) return;

    const float4* xp = (const float4*)(X + (size_t)n * F_DIM);
    float acc[C_DIM];
#pragma unroll
    for (int c = 0; c < C_DIM; ++c) acc[c] = 0.0f;

#pragma unroll 1
    for (int ch = 0; ch < 8; ++ch) {
        float4 xv[4];
#pragma unroll
        for (int j = 0; j < 4; ++j) xv[j] = xp[ch * 4 + j];
#pragma unroll
        for (int c = 0; c < C_DIM; ++c) {
            const float4* wp = (const float4*)(ws + c * F_DIM + ch * 16);
            float s = acc[c];
#pragma unroll
            for (int j = 0; j < 4; ++j) {
                float4 w = wp[j];
                s += xv[j].x * w.x + xv[j].y * w.y + xv[j].z * w.z + xv[j].w * w.w;
            }
            acc[c] = s;
        }
    }

    float dn = g_dinv[n];
    float4* yp = (float4*)(Y + (size_t)n * C_DIM);
#pragma unroll
    for (int k = 0; k < 10; ++k)
        yp[k] = make_float4(dn * acc[4 * k], dn * acc[4 * k + 1],
                            dn * acc[4 * k + 2], dn * acc[4 * k + 3]);
}

// One hop on pre-scaled data: dst[n] = dinv[n]^(2 or 1) * (src[n] + sum src[r]).
// 10 threads per node, one float4 (16B) each: a node's 10 lanes cover the full
// 160B row -> perfectly coalesced neighbor reads; 1M light threads hide latency.
__global__ void k_gather(const float4* __restrict__ src, float4* __restrict__ dst,
                         int N, int squared) {
    int t = blockIdx.x * blockDim.x + threadIdx.x;
    int n = t / 10;
    if (n >= N) return;
    int part = t - n * 10;

    int beg = g_off[n];
    int end = beg + g_deg[n];
    size_t pbase = part;

    float4 a = src[(size_t)n * 10 + pbase];

    int k = beg;
#pragma unroll 1
    for (; k + 4 <= end; k += 4) {
        int r0 = g_adj[k];
        int r1 = g_adj[k + 1];
        int r2 = g_adj[k + 2];
        int r3 = g_adj[k + 3];
        float4 v0 = src[(size_t)r0 * 10 + pbase];
        float4 v1 = src[(size_t)r1 * 10 + pbase];
        float4 v2 = src[(size_t)r2 * 10 + pbase];
        float4 v3 = src[(size_t)r3 * 10 + pbase];
        a.x += (v0.x + v1.x) + (v2.x + v3.x);
        a.y += (v0.y + v1.y) + (v2.y + v3.y);
        a.z += (v0.z + v1.z) + (v2.z + v3.z);
        a.w += (v0.w + v1.w) + (v2.w + v3.w);
    }
#pragma unroll 1
    for (; k < end; ++k) {
        int r0 = g_adj[k];
        float4 v0 = src[(size_t)r0 * 10 + pbase];
        a.x += v0.x; a.y += v0.y; a.z += v0.z; a.w += v0.w;
    }

    float dn = g_dinv[n];
    float sc = squared ? dn * dn : dn;
    dst[(size_t)n * 10 + pbase] = make_float4(sc * a.x, sc * a.y, sc * a.z, sc * a.w);
}

// out[n, :] = log_softmax(src[n, :] + bias)
__global__ void k_lsm(const float* __restrict__ src, const float* __restrict__ bias,
                      float* __restrict__ out, int N) {
    int n = blockIdx.x * blockDim.x + threadIdx.x;
    if (n >= N) return;
    float z[C_DIM];
    const float4* s = (const float4*)(src + (size_t)n * C_DIM);
#pragma unroll
    for (int k = 0; k < 10; ++k) {
        float4 v = s[k];
        z[4 * k + 0] = v.x + bias[4 * k + 0];
        z[4 * k + 1] = v.y + bias[4 * k + 1];
        z[4 * k + 2] = v.z + bias[4 * k + 2];
        z[4 * k + 3] = v.w + bias[4 * k + 3];
    }
    float m = z[0];
#pragma unroll
    for (int c = 1; c < C_DIM; ++c) m = fmaxf(m, z[c]);
    float sum = 0.0f;
#pragma unroll
    for (int c = 0; c < C_DIM; ++c) sum += __expf(z[c] - m);
    float l = m + logf(sum);
    float4* o = (float4*)(out + (size_t)n * C_DIM);
#pragma unroll
    for (int k = 0; k < 10; ++k)
        o[k] = make_float4(z[4 * k] - l, z[4 * k + 1] - l, z[4 * k + 2] - l, z[4 * k + 3] - l);
}

// ---------------- launch ----------------
extern "C" void kernel_launch(void* const* d_in, const int* in_sizes, int n_in,
                              void* d_out, int out_size) {
    const float* X    = (const float*)d_in[0];      // [N, 128]
    const float* W    = (const float*)d_in[1];      // [40, 128]
    const float* bias = (const float*)d_in[2];      // [40]
    const int*   ei   = (const int*)d_in[3];        // [2, E] int32 or int64
    (void)n_in;

    const int N = in_sizes[0] / F_DIM;
    const int E = in_sizes[3] / 2;
    const int ce = (E + NCOPY - 1) / NCOPY;
    float* out = (float*)d_out;
    (void)out_size;

    const int TB = 256;
    const int NB = (N + TB - 1) / TB;
    dim3 gN(NB);
    dim3 gE((E + TB - 1) / TB);
    dim3 gZ(((size_t)NCOPY * N_MAX / 4 + TB - 1) / TB);

    // CSR build (privatized counting sort)
    k_detect<<<1, 32>>>(ei, E);
    k_zero_hist<<<gZ, TB>>>();
    k_hist<<<gE, TB>>>(ei, E, ce);
    k_deg<<<gN, TB>>>(N);
    k_scanp<<<1, 512>>>(NB);
    k_base<<<gN, TB>>>(N);
    k_fill<<<gE, TB>>>(ei, E, ce);

    // projection (128 -> 40) with D^{-1/2} prescale fused
    k_gemm<<<gN, TB>>>(X, W, g_bufB, N);

    // hops: 10 threads/node, 1 float4 each
    const int GB = 320;
    dim3 gG(((size_t)N * 10 + GB - 1) / GB);
    k_gather<<<gG, GB>>>((const float4*)g_bufB, (float4*)g_bufA, N, 1);
    k_gather<<<gG, GB>>>((const float4*)g_bufA, (float4*)g_bufB, N, 0);

    // bias + log_softmax
    k_lsm<<<gN, TB>>>(g_bufB, bias, out, N);
}